// round 10
// baseline (speedup 1.0000x reference)
#include <cuda_runtime.h>
#include <math.h>

// Problem constants
#define MM       2048           // patches
#define NC       4              // compartments
#define NSTEPS   128
#define BETA_F   0.25f
#define TRAJ_ELEMS (NSTEPS * MM * (NC + 1))   // 1310720

// 128 persistent blocks, 16 rows of R each, 256 threads.
// SMEM ~136KB => 1 block/SM => all 128 blocks co-resident (148/152 SMs),
// so the software grid barrier cannot deadlock.
#define NBLK     128
#define ROWS     16
#define NTHREADS 256
#define NGRP     16             // barrier tree: 16 groups x 8 blocks
#define NCOPY    8              // broadcast flag copies (one L2 line each)
#define PAD      32             // 32 uints = 128B padding between counters

// SMEM: R tile (16*2048 f32) + x vector (2048 f32) + 32 partials + 16 doubles
#define SMEM_BYTES ((ROWS * MM + MM + 32) * 4 + 16 * 8)

// -------- persistent device state (monotonic / re-derived every launch) -----
__device__ float        g_x[MM];              // rho[:,0] (phase-A input)
__device__ float        g_p[MM];              // infect_prob (phase-B input)
__device__ float        g_part[NBLK * MM];    // per-block column partials
__device__ double       g_bsum[NBLK];         // per-block |traj| sums
__device__ unsigned int g_grp[NGRP * PAD];    // group arrival counters (padded)
__device__ unsigned int g_root_ctr;           // root arrival counter
__device__ unsigned int g_flag[NCOPY * PAD];  // released generation (8 copies)

// Grid barrier, one component changed vs R9 (which matched R3 at ~2.0us):
// the WAIT. R3/R9 used __nanosleep(64) polling; NANOSLEEP granularity is
// coarse (effective ~0.5-1us), so barrier exit was gated by sleep quantization,
// not by release latency. Here: SLEEPLESS relaxed polling, 1 poller per block,
// spread over 8 padded flag copies (16 pollers/line). Spin traffic is
// 128 LDGs per ~600cyc round-trip — ~4 orders of magnitude under the LTS cap
// (the R4/R7 collapses were 1K-16K unthrottled pollers, a different regime).
// Arrival: R9's proven plain-relaxed tree (8 contenders/group, 16 at root)
// with __threadfence for publish. Release: root-last atomicExch on all 8
// copies (independent, latencies overlap). Monotonic => graph-replay safe.
__device__ __forceinline__ void gridsync(unsigned int target) {
    __syncthreads();
    if (threadIdx.x == 0) {
        __threadfence();                                  // publish prior stores
        unsigned int v = atomicAdd(&g_grp[(blockIdx.x >> 3) * PAD], 1u);
        if (v == target * 8u - 1u) {                      // last of my 8-block group
            unsigned int r = atomicAdd(&g_root_ctr, 1u);
            if (r == target * (unsigned)NGRP - 1u) {      // last block overall
                #pragma unroll
                for (int i = 0; i < NCOPY; i++)
                    atomicExch(&g_flag[i * PAD], target); // release: 8 copies
            }
        }
        const volatile unsigned int* myflag =
            &g_flag[(blockIdx.x & (NCOPY - 1)) * PAD];
        while ((int)(*myflag - target) < 0) { }           // sleepless spin
    }
    __syncthreads();
}

__global__ void __launch_bounds__(NTHREADS, 1)
metasim_kernel(const float* __restrict__ Rg,
               const float* __restrict__ Tg,
               const float* __restrict__ rho0,
               float* __restrict__ out,
               int out_size)
{
    extern __shared__ float smem[];
    float*  Rs   = smem;                   // [ROWS][MM]
    float*  xs   = Rs + ROWS * MM;         // [MM] staged vector
    float*  part = xs + MM;                // [16 rows][2 halves]
    double* dsum = (double*)(part + 32);   // [16], 8B aligned

    const int tid     = threadIdx.x;
    const int blk     = blockIdx.x;
    const int w       = tid >> 5;
    const int lane    = tid & 31;
    const int rowbase = blk * ROWS;
    const int rgrp    = w >> 1;            // 4-row group 0..3
    const int colhalf = w & 1;             // 0: cols 0..1023, 1: 1024..2047
    const int row0    = 4 * rgrp;

    // starting generation (all flag copies equal at every launch boundary)
    unsigned int gen = *((volatile unsigned int*)&g_flag[0]);

    // ---- load this block's 16 rows of R into SMEM (once) ----
    {
        const float4* Rg4 = (const float4*)Rg + (size_t)rowbase * (MM / 4);
        float4* Rs4 = (float4*)Rs;
        #pragma unroll 4
        for (int k = tid; k < ROWS * MM / 4; k += NTHREADS) Rs4[k] = Rg4[k];
    }

    // ---- per-row state lives in tid<16 ----
    const int myrow = rowbase + tid;       // valid for tid < ROWS
    float r0 = 0.f, r1 = 0.f, r2 = 0.f, r3 = 0.f, kk = 0.f;
    float Tr[16];
    if (tid < ROWS) {
        #pragma unroll
        for (int i = 0; i < 16; i++) Tr[i] = Tg[i];
        r0 = rho0[myrow * 4 + 0];
        r1 = rho0[myrow * 4 + 1];
        r2 = rho0[myrow * 4 + 2];
        r3 = rho0[myrow * 4 + 3];
        __stcg(&g_x[myrow], r0);           // initial x = rho0[:,0]
    }
    __syncthreads();                       // Rs ready for column sums

    // ---- deterministic ntot: per-block column partials (no float atomics) --
    for (int c = tid; c < MM; c += NTHREADS) {
        float s = 0.f;
        #pragma unroll
        for (int r = 0; r < ROWS; r++) s += Rs[r * MM + c];
        __stcg(&g_part[blk * MM + c], s);
    }
    gen++; gridsync(gen);                  // partials + g_x visible grid-wide

    if (tid < ROWS) {                      // ntot for own rows, fixed sum order
        float s = 0.f;
        #pragma unroll 8
        for (int bb = 0; bb < NBLK; bb++) s += __ldcg(&g_part[bb * MM + myrow]);
        kk = -BETA_F / s;
    }

    // warp's 4 R-row pointers over its column half (float4 granularity)
    const float4* Ra = (const float4*)(Rs + (row0 + 0) * MM) + colhalf * 256 + lane;
    const float4* Rb = (const float4*)(Rs + (row0 + 1) * MM) + colhalf * 256 + lane;
    const float4* Rc = (const float4*)(Rs + (row0 + 2) * MM) + colhalf * 256 + lane;
    const float4* Rd = (const float4*)(Rs + (row0 + 3) * MM) + colhalf * 256 + lane;
    float4* xs4  = (float4*)xs;
    const float4* xw = xs4 + colhalf * 256 + lane;

    double dAcc = 0.0;

    for (int t = 0; t < NSTEPS; t++) {
        // ===== Phase A: frac = R @ x ; p = 1 - exp(-beta*frac/ntot) =====
        {
            const float4* gx4 = (const float4*)g_x;
            xs4[tid]       = __ldcg(gx4 + tid);
            xs4[tid + 256] = __ldcg(gx4 + tid + 256);
        }
        __syncthreads();
        {
            float a0 = 0.f, a1 = 0.f, a2 = 0.f, a3 = 0.f;
            #pragma unroll 4
            for (int j = 0; j < 8; j++) {
                const float4 xv = xw[j * 32];
                const float4 u0 = Ra[j * 32];
                const float4 u1 = Rb[j * 32];
                const float4 u2 = Rc[j * 32];
                const float4 u3 = Rd[j * 32];
                a0 += u0.x*xv.x + u0.y*xv.y + u0.z*xv.z + u0.w*xv.w;
                a1 += u1.x*xv.x + u1.y*xv.y + u1.z*xv.z + u1.w*xv.w;
                a2 += u2.x*xv.x + u2.y*xv.y + u2.z*xv.z + u2.w*xv.w;
                a3 += u3.x*xv.x + u3.y*xv.y + u3.z*xv.z + u3.w*xv.w;
            }
            #pragma unroll
            for (int o = 16; o; o >>= 1) {
                a0 += __shfl_xor_sync(0xffffffffu, a0, o);
                a1 += __shfl_xor_sync(0xffffffffu, a1, o);
                a2 += __shfl_xor_sync(0xffffffffu, a2, o);
                a3 += __shfl_xor_sync(0xffffffffu, a3, o);
            }
            if (lane == 0) {
                part[(row0 + 0) * 2 + colhalf] = a0;
                part[(row0 + 1) * 2 + colhalf] = a1;
                part[(row0 + 2) * 2 + colhalf] = a2;
                part[(row0 + 3) * 2 + colhalf] = a3;
            }
        }
        __syncthreads();
        if (tid < ROWS) {
            const float fr = part[2 * tid] + part[2 * tid + 1];
            __stcg(&g_p[myrow], 1.0f - expf(kk * fr));
        }
        gen++; gridsync(gen);

        // ===== Phase B: nw = R @ p ; compartment update ; traj out =====
        {
            const float4* gp4 = (const float4*)g_p;
            xs4[tid]       = __ldcg(gp4 + tid);
            xs4[tid + 256] = __ldcg(gp4 + tid + 256);
        }
        __syncthreads();
        {
            float a0 = 0.f, a1 = 0.f, a2 = 0.f, a3 = 0.f;
            #pragma unroll 4
            for (int j = 0; j < 8; j++) {
                const float4 xv = xw[j * 32];
                const float4 u0 = Ra[j * 32];
                const float4 u1 = Rb[j * 32];
                const float4 u2 = Rc[j * 32];
                const float4 u3 = Rd[j * 32];
                a0 += u0.x*xv.x + u0.y*xv.y + u0.z*xv.z + u0.w*xv.w;
                a1 += u1.x*xv.x + u1.y*xv.y + u1.z*xv.z + u1.w*xv.w;
                a2 += u2.x*xv.x + u2.y*xv.y + u2.z*xv.z + u2.w*xv.w;
                a3 += u3.x*xv.x + u3.y*xv.y + u3.z*xv.z + u3.w*xv.w;
            }
            #pragma unroll
            for (int o = 16; o; o >>= 1) {
                a0 += __shfl_xor_sync(0xffffffffu, a0, o);
                a1 += __shfl_xor_sync(0xffffffffu, a1, o);
                a2 += __shfl_xor_sync(0xffffffffu, a2, o);
                a3 += __shfl_xor_sync(0xffffffffu, a3, o);
            }
            if (lane == 0) {
                part[(row0 + 0) * 2 + colhalf] = a0;
                part[(row0 + 1) * 2 + colhalf] = a1;
                part[(row0 + 2) * 2 + colhalf] = a2;
                part[(row0 + 3) * 2 + colhalf] = a3;
            }
        }
        __syncthreads();
        if (tid < ROWS) {
            const float acc = part[2 * tid] + part[2 * tid + 1];
            const float s   = r0 + r1 + r2 + r3;
            const float nw  = (1.0f - s) * acc;
            float n0 = r0 * Tr[0] + r1 * Tr[4] + r2 * Tr[8]  + r3 * Tr[12] + nw;
            float n1 = r0 * Tr[1] + r1 * Tr[5] + r2 * Tr[9]  + r3 * Tr[13];
            float n2 = r0 * Tr[2] + r1 * Tr[6] + r2 * Tr[10] + r3 * Tr[14];
            float n3 = r0 * Tr[3] + r1 * Tr[7] + r2 * Tr[11] + r3 * Tr[15];
            n0 = fminf(fmaxf(n0, 0.0f), 1e10f);
            n1 = fminf(fmaxf(n1, 0.0f), 1e10f);
            n2 = fminf(fmaxf(n2, 0.0f), 1e10f);
            n3 = fminf(fmaxf(n3, 0.0f), 1e10f);
            r0 = n0; r1 = n1; r2 = n2; r3 = n3;
            __stcg(&g_x[myrow], n0);                      // next step's x

            const float S = 1.0f - (n0 + n1 + n2 + n3);   // AddSusceptibleLayer
            float* o = out + ((size_t)t * MM + myrow) * (NC + 1);
            o[0] = S; o[1] = n0; o[2] = n1; o[3] = n2; o[4] = n3;
            dAcc += (double)(fabsf(S) + fabsf(n0) + fabsf(n1) + fabsf(n2) + fabsf(n3));
        }
        gen++; gridsync(gen);
    }

    // ---- agreement = mean(|traj|), fully deterministic reduction ----
    if (tid < ROWS) dsum[tid] = dAcc;
    __syncthreads();
    if (tid == 0) {
        double s = 0.0;
        for (int i = 0; i < ROWS; i++) s += dsum[i];
        g_bsum[blk] = s;
    }
    gen++; gridsync(gen);
    if (blk == 0 && tid == 0 && out_size > TRAJ_ELEMS) {
        double s = 0.0;
        for (int i = 0; i < NBLK; i++) s += __ldcg(&g_bsum[i]);
        out[TRAJ_ELEMS] = (float)(s / (double)TRAJ_ELEMS);
    }
}

extern "C" void kernel_launch(void* const* d_in, const int* in_sizes, int n_in,
                              void* d_out, int out_size)
{
    // Identify inputs by element count: R: 2048*2048, T: 4*4, rho0: 2048*4
    const float* R    = nullptr;
    const float* Tm   = nullptr;
    const float* rho0 = nullptr;
    for (int i = 0; i < n_in; i++) {
        if      (in_sizes[i] == MM * MM) R    = (const float*)d_in[i];
        else if (in_sizes[i] == NC * NC) Tm   = (const float*)d_in[i];
        else if (in_sizes[i] == MM * NC) rho0 = (const float*)d_in[i];
    }
    if (!R    && n_in > 0) R    = (const float*)d_in[0];
    if (!Tm   && n_in > 1) Tm   = (const float*)d_in[1];
    if (!rho0 && n_in > 2) rho0 = (const float*)d_in[2];

    cudaFuncSetAttribute(metasim_kernel,
                         cudaFuncAttributeMaxDynamicSharedMemorySize,
                         SMEM_BYTES);

    metasim_kernel<<<NBLK, NTHREADS, SMEM_BYTES>>>(R, Tm, rho0,
                                                   (float*)d_out, out_size);
}

// round 12
// speedup vs baseline: 1.0809x; 1.0809x over previous
#include <cuda_runtime.h>
#include <math.h>

// Problem constants
#define MM       2048           // patches
#define NC       4              // compartments
#define NSTEPS   128
#define BETA_F   0.25f
#define TRAJ_ELEMS (NSTEPS * MM * (NC + 1))   // 1310720

// 128 persistent blocks, 16 rows of R each, 256 threads.
// SMEM ~136KB => 1 block/SM => all 128 blocks co-resident (148/152 SMs),
// so the software grid barrier cannot deadlock.
#define NBLK     128
#define ROWS     16
#define NTHREADS 256
#define NGRP     16             // barrier tree: 16 groups x 8 blocks
#define PAD      32             // 32 uints = 128B: one word per L2 line

// SMEM: R tile (16*2048 f32) + x vector (2048 f32) + 32 partials + 16 doubles
#define SMEM_BYTES ((ROWS * MM + MM + 32) * 4 + 16 * 8)

// -------- persistent device state (monotonic / re-derived every launch) -----
__device__ float        g_x[MM];             // rho[:,0] (phase-A input)
__device__ float        g_p[MM];             // infect_prob (phase-B input)
__device__ float        g_part[NBLK * MM];   // per-block column partials
__device__ double       g_bsum[NBLK];        // per-block |traj| sums
__device__ unsigned int g_grp[NGRP * PAD];   // group arrival counters (padded)
__device__ unsigned int g_root_ctr;          // root arrival counter
__device__ unsigned int g_flag[NBLK * PAD];  // per-block release flag (padded)

// Grid barrier v6 — fence-fence synchronization with GPU-scope RELAXED flags.
// Primitive ledger from R3-R11:
//   toxic:  SYS-scope volatile polls (R10), acquire-per-poll (R5/R7/R8),
//           __nanosleep waits (R3/R9 floor), weak/weak flags (R11: RACY)
//   cheap:  relaxed atomicAdd (ATOMG), __threadfence
// This design is the formally-correct C++-style pattern built only from the
// cheap set + GPU-scope relaxed strong ld/st (relaxed = strong op in PTX =>
// morally-strong pairing, but no per-poll ordering cost):
//   ARRIVAL:   __threadfence ; relaxed atomicAdd tree (8/group, 16 root)
//   RELEASE:   root-last block: __threadfence (release side) ; warp 0 writes
//              generation to all 128 per-block padded flags via st.relaxed.gpu
//   WAIT:      each block's thread 0 polls ITS OWN flag via ld.relaxed.gpu
//              (dependent load loop: self-throttled to ~1 poll per L2 RTT),
//              then __threadfence (acquire side) before any data reads.
// HB chain: arriver fence -> RMW  ==>  releaser RMW-observe -> fence -> flag
// store  ==>  waiter flag load -> fence -> data reads. Every link is a
// morally-strong same-address pair + cumulative fence.
// Monotonic generations => safe across CUDA-graph replays.
__device__ __forceinline__ void gridsync(unsigned int target) {
    __syncthreads();
    if (threadIdx.x < 32) {
        unsigned int rel = 0;
        if (threadIdx.x == 0) {
            __threadfence();                              // publish prior stores
            unsigned int v = atomicAdd(&g_grp[(blockIdx.x >> 3) * PAD], 1u);
            if (v == target * 8u - 1u) {                  // last of my 8-block group
                unsigned int r = atomicAdd(&g_root_ctr, 1u);
                rel = (r == target * (unsigned)NGRP - 1u) ? 1u : 0u;
            }
        }
        rel = __shfl_sync(0xffffffffu, rel, 0);
        if (rel) {                                        // releasing block only
            __threadfence();                              // release-side fence
            #pragma unroll
            for (int i = 0; i < NBLK / 32; i++) {
                unsigned int* f = &g_flag[(threadIdx.x + i * 32) * PAD];
                asm volatile("st.relaxed.gpu.u32 [%0], %1;"
                             :: "l"(f), "r"(target) : "memory");
            }
        }
        if (threadIdx.x == 0) {
            const unsigned int* myf = &g_flag[blockIdx.x * PAD];
            unsigned int f;
            do {   // dependent relaxed load: one L2 round trip per iteration
                asm volatile("ld.relaxed.gpu.u32 %0, [%1];"
                             : "=r"(f) : "l"(myf) : "memory");
            } while ((int)(f - target) < 0);
            __threadfence();                              // acquire-side fence
        }
    }
    __syncthreads();
}

__global__ void __launch_bounds__(NTHREADS, 1)
metasim_kernel(const float* __restrict__ Rg,
               const float* __restrict__ Tg,
               const float* __restrict__ rho0,
               float* __restrict__ out,
               int out_size)
{
    extern __shared__ float smem[];
    float*  Rs   = smem;                   // [ROWS][MM]
    float*  xs   = Rs + ROWS * MM;         // [MM] staged vector
    float*  part = xs + MM;                // [16 rows][2 halves]
    double* dsum = (double*)(part + 32);   // [16], 8B aligned

    const int tid     = threadIdx.x;
    const int blk     = blockIdx.x;
    const int w       = tid >> 5;
    const int lane    = tid & 31;
    const int rowbase = blk * ROWS;
    const int rgrp    = w >> 1;            // 4-row group 0..3
    const int colhalf = w & 1;             // 0: cols 0..1023, 1: 1024..2047
    const int row0    = 4 * rgrp;

    // starting generation (all flags equal at every launch boundary)
    unsigned int gen;
    {
        const unsigned int* myf = &g_flag[blk * PAD];
        asm volatile("ld.relaxed.gpu.u32 %0, [%1];" : "=r"(gen) : "l"(myf) : "memory");
    }

    // ---- load this block's 16 rows of R into SMEM (once) ----
    {
        const float4* Rg4 = (const float4*)Rg + (size_t)rowbase * (MM / 4);
        float4* Rs4 = (float4*)Rs;
        #pragma unroll 4
        for (int k = tid; k < ROWS * MM / 4; k += NTHREADS) Rs4[k] = Rg4[k];
    }

    // ---- per-row state lives in tid<16 ----
    const int myrow = rowbase + tid;       // valid for tid < ROWS
    float r0 = 0.f, r1 = 0.f, r2 = 0.f, r3 = 0.f, kk = 0.f;
    float Tr[16];
    if (tid < ROWS) {
        #pragma unroll
        for (int i = 0; i < 16; i++) Tr[i] = Tg[i];
        r0 = rho0[myrow * 4 + 0];
        r1 = rho0[myrow * 4 + 1];
        r2 = rho0[myrow * 4 + 2];
        r3 = rho0[myrow * 4 + 3];
        __stcg(&g_x[myrow], r0);           // initial x = rho0[:,0]
    }
    __syncthreads();                       // Rs ready for column sums

    // ---- deterministic ntot: per-block column partials (no float atomics) --
    for (int c = tid; c < MM; c += NTHREADS) {
        float s = 0.f;
        #pragma unroll
        for (int r = 0; r < ROWS; r++) s += Rs[r * MM + c];
        __stcg(&g_part[blk * MM + c], s);
    }
    gen++; gridsync(gen);                  // partials + g_x visible grid-wide

    if (tid < ROWS) {                      // ntot for own rows, fixed sum order
        float s = 0.f;
        #pragma unroll 8
        for (int bb = 0; bb < NBLK; bb++) s += __ldcg(&g_part[bb * MM + myrow]);
        kk = -BETA_F / s;
    }

    // warp's 4 R-row pointers over its column half (float4 granularity)
    const float4* Ra = (const float4*)(Rs + (row0 + 0) * MM) + colhalf * 256 + lane;
    const float4* Rb = (const float4*)(Rs + (row0 + 1) * MM) + colhalf * 256 + lane;
    const float4* Rc = (const float4*)(Rs + (row0 + 2) * MM) + colhalf * 256 + lane;
    const float4* Rd = (const float4*)(Rs + (row0 + 3) * MM) + colhalf * 256 + lane;
    float4* xs4  = (float4*)xs;
    const float4* xw = xs4 + colhalf * 256 + lane;

    double dAcc = 0.0;

    for (int t = 0; t < NSTEPS; t++) {
        // ===== Phase A: frac = R @ x ; p = 1 - exp(-beta*frac/ntot) =====
        {
            const float4* gx4 = (const float4*)g_x;
            xs4[tid]       = __ldcg(gx4 + tid);
            xs4[tid + 256] = __ldcg(gx4 + tid + 256);
        }
        __syncthreads();
        {
            float a0 = 0.f, a1 = 0.f, a2 = 0.f, a3 = 0.f;
            #pragma unroll 4
            for (int j = 0; j < 8; j++) {
                const float4 xv = xw[j * 32];
                const float4 u0 = Ra[j * 32];
                const float4 u1 = Rb[j * 32];
                const float4 u2 = Rc[j * 32];
                const float4 u3 = Rd[j * 32];
                a0 += u0.x*xv.x + u0.y*xv.y + u0.z*xv.z + u0.w*xv.w;
                a1 += u1.x*xv.x + u1.y*xv.y + u1.z*xv.z + u1.w*xv.w;
                a2 += u2.x*xv.x + u2.y*xv.y + u2.z*xv.z + u2.w*xv.w;
                a3 += u3.x*xv.x + u3.y*xv.y + u3.z*xv.z + u3.w*xv.w;
            }
            #pragma unroll
            for (int o = 16; o; o >>= 1) {
                a0 += __shfl_xor_sync(0xffffffffu, a0, o);
                a1 += __shfl_xor_sync(0xffffffffu, a1, o);
                a2 += __shfl_xor_sync(0xffffffffu, a2, o);
                a3 += __shfl_xor_sync(0xffffffffu, a3, o);
            }
            if (lane == 0) {
                part[(row0 + 0) * 2 + colhalf] = a0;
                part[(row0 + 1) * 2 + colhalf] = a1;
                part[(row0 + 2) * 2 + colhalf] = a2;
                part[(row0 + 3) * 2 + colhalf] = a3;
            }
        }
        __syncthreads();
        if (tid < ROWS) {
            const float fr = part[2 * tid] + part[2 * tid + 1];
            __stcg(&g_p[myrow], 1.0f - expf(kk * fr));
        }
        gen++; gridsync(gen);

        // ===== Phase B: nw = R @ p ; compartment update ; traj out =====
        {
            const float4* gp4 = (const float4*)g_p;
            xs4[tid]       = __ldcg(gp4 + tid);
            xs4[tid + 256] = __ldcg(gp4 + tid + 256);
        }
        __syncthreads();
        {
            float a0 = 0.f, a1 = 0.f, a2 = 0.f, a3 = 0.f;
            #pragma unroll 4
            for (int j = 0; j < 8; j++) {
                const float4 xv = xw[j * 32];
                const float4 u0 = Ra[j * 32];
                const float4 u1 = Rb[j * 32];
                const float4 u2 = Rc[j * 32];
                const float4 u3 = Rd[j * 32];
                a0 += u0.x*xv.x + u0.y*xv.y + u0.z*xv.z + u0.w*xv.w;
                a1 += u1.x*xv.x + u1.y*xv.y + u1.z*xv.z + u1.w*xv.w;
                a2 += u2.x*xv.x + u2.y*xv.y + u2.z*xv.z + u2.w*xv.w;
                a3 += u3.x*xv.x + u3.y*xv.y + u3.z*xv.z + u3.w*xv.w;
            }
            #pragma unroll
            for (int o = 16; o; o >>= 1) {
                a0 += __shfl_xor_sync(0xffffffffu, a0, o);
                a1 += __shfl_xor_sync(0xffffffffu, a1, o);
                a2 += __shfl_xor_sync(0xffffffffu, a2, o);
                a3 += __shfl_xor_sync(0xffffffffu, a3, o);
            }
            if (lane == 0) {
                part[(row0 + 0) * 2 + colhalf] = a0;
                part[(row0 + 1) * 2 + colhalf] = a1;
                part[(row0 + 2) * 2 + colhalf] = a2;
                part[(row0 + 3) * 2 + colhalf] = a3;
            }
        }
        __syncthreads();
        if (tid < ROWS) {
            const float acc = part[2 * tid] + part[2 * tid + 1];
            const float s   = r0 + r1 + r2 + r3;
            const float nw  = (1.0f - s) * acc;
            float n0 = r0 * Tr[0] + r1 * Tr[4] + r2 * Tr[8]  + r3 * Tr[12] + nw;
            float n1 = r0 * Tr[1] + r1 * Tr[5] + r2 * Tr[9]  + r3 * Tr[13];
            float n2 = r0 * Tr[2] + r1 * Tr[6] + r2 * Tr[10] + r3 * Tr[14];
            float n3 = r0 * Tr[3] + r1 * Tr[7] + r2 * Tr[11] + r3 * Tr[15];
            n0 = fminf(fmaxf(n0, 0.0f), 1e10f);
            n1 = fminf(fmaxf(n1, 0.0f), 1e10f);
            n2 = fminf(fmaxf(n2, 0.0f), 1e10f);
            n3 = fminf(fmaxf(n3, 0.0f), 1e10f);
            r0 = n0; r1 = n1; r2 = n2; r3 = n3;
            __stcg(&g_x[myrow], n0);                      // next step's x

            const float S = 1.0f - (n0 + n1 + n2 + n3);   // AddSusceptibleLayer
            float* o = out + ((size_t)t * MM + myrow) * (NC + 1);
            o[0] = S; o[1] = n0; o[2] = n1; o[3] = n2; o[4] = n3;
            dAcc += (double)(fabsf(S) + fabsf(n0) + fabsf(n1) + fabsf(n2) + fabsf(n3));
        }
        gen++; gridsync(gen);
    }

    // ---- agreement = mean(|traj|), fully deterministic reduction ----
    if (tid < ROWS) dsum[tid] = dAcc;
    __syncthreads();
    if (tid == 0) {
        double s = 0.0;
        for (int i = 0; i < ROWS; i++) s += dsum[i];
        g_bsum[blk] = s;
    }
    gen++; gridsync(gen);
    if (blk == 0 && tid == 0 && out_size > TRAJ_ELEMS) {
        double s = 0.0;
        for (int i = 0; i < NBLK; i++) s += __ldcg(&g_bsum[i]);
        out[TRAJ_ELEMS] = (float)(s / (double)TRAJ_ELEMS);
    }
}

extern "C" void kernel_launch(void* const* d_in, const int* in_sizes, int n_in,
                              void* d_out, int out_size)
{
    // Identify inputs by element count: R: 2048*2048, T: 4*4, rho0: 2048*4
    const float* R    = nullptr;
    const float* Tm   = nullptr;
    const float* rho0 = nullptr;
    for (int i = 0; i < n_in; i++) {
        if      (in_sizes[i] == MM * MM) R    = (const float*)d_in[i];
        else if (in_sizes[i] == NC * NC) Tm   = (const float*)d_in[i];
        else if (in_sizes[i] == MM * NC) rho0 = (const float*)d_in[i];
    }
    if (!R    && n_in > 0) R    = (const float*)d_in[0];
    if (!Tm   && n_in > 1) Tm   = (const float*)d_in[1];
    if (!rho0 && n_in > 2) rho0 = (const float*)d_in[2];

    cudaFuncSetAttribute(metasim_kernel,
                         cudaFuncAttributeMaxDynamicSharedMemorySize,
                         SMEM_BYTES);

    metasim_kernel<<<NBLK, NTHREADS, SMEM_BYTES>>>(R, Tm, rho0,
                                                   (float*)d_out, out_size);
}

// round 13
// speedup vs baseline: 1.3907x; 1.2866x over previous
#include <cuda_runtime.h>
#include <math.h>

// Problem constants
#define MM       2048           // patches
#define NC       4              // compartments
#define NSTEPS   128
#define BETA_F   0.25f
#define TRAJ_ELEMS (NSTEPS * MM * (NC + 1))   // 1310720

// Launch geometry: 128 persistent blocks, 16 rows of R each, 256 threads
// (8 warps x 2 rows/warp). 1 block/SM via smem footprint => co-residency
// guaranteed on 148/152-SM GB300, so the software grid barrier cannot deadlock.
#define NBLK     128
#define ROWS     16
#define NTHREADS 256

// SMEM: R tile (16*2048 f32) + x vector (2048 f32) + ntot (16 f32) + 16 doubles
#define SMEM_BYTES ((ROWS * MM + MM + 16) * 4 + 16 * 8)

// -------- persistent device state (re-initialized every launch) --------
__device__ float        g_x[MM];            // rho[:,0] (phase-A input vector)
__device__ float        g_p[MM];            // infect_prob (phase-B input vector)
__device__ float        g_part[NBLK * MM];  // per-block column partial sums (ntot)
__device__ double       g_bsum[NBLK];       // per-block |traj| sums (agreement)
__device__ unsigned int g_bar_in  = 0;      // monotonic arrival counter
__device__ unsigned int g_bar_gen = 0;      // monotonic generation counter

// R3's champion barrier (1.9us) with ONE change: the wait. R3 used a
// volatile (SYS-scope) poll throttled by __nanosleep(64); the sleep's
// 0.5-1us wake quantization was the dominant removable term. Replaced by a
// sleepless GPU-scope RELAXED poll of the single release word:
//  - relaxed GPU-scope strong loads measured non-toxic in R12 (no phantom
//    HBM, correct), unlike SYS-volatile (R10) and acquire-per-poll (R5/7/8)
//  - single release word: one atomicAdd by the last arriver, no R12-style
//    128-store broadcast fan-out
//  - 128 pollers, each self-throttled to one load per L2 round trip by the
//    dependent poll loop => ~0.2 req/cyc on one line, far under LTS caps
//  - __threadfence after poll success = acquire side (R12-proven pattern);
//    __syncthreads extends the ordering to the whole block
// Monotonic counters => safe across CUDA-graph replays (each launch reads
// the current generation first; invariant g_bar_in == gen*NBLK at entry).
__device__ __forceinline__ void gridsync(unsigned int &gen) {
    __syncthreads();
    if (threadIdx.x == 0) {
        __threadfence();                                   // publish writes (release)
        unsigned int a = atomicAdd(&g_bar_in, 1u);
        if (a == gen * (unsigned)NBLK + (unsigned)(NBLK - 1)) {
            atomicAdd(&g_bar_gen, 1u);                     // last arriver releases
        } else {
            unsigned int f;
            do {   // dependent relaxed load: one L2 round trip per iteration
                asm volatile("ld.relaxed.gpu.u32 %0, [%1];"
                             : "=r"(f) : "l"(&g_bar_gen) : "memory");
            } while ((int)(f - (gen + 1u)) < 0);
            __threadfence();                               // acquire side
        }
        gen++;
    }
    __syncthreads();
}

__global__ void __launch_bounds__(NTHREADS, 1)
metasim_kernel(const float* __restrict__ Rg,
               const float* __restrict__ Tg,
               const float* __restrict__ rho0,
               float* __restrict__ out,
               int out_size)
{
    extern __shared__ float smem[];
    float*  Rs     = smem;                 // [ROWS][MM]
    float*  xs     = Rs + ROWS * MM;       // [MM]
    float*  ntot_s = xs + MM;              // [ROWS]
    double* dsum   = (double*)(ntot_s + 16); // [16], 8B-aligned

    const int tid     = threadIdx.x;
    const int blk     = blockIdx.x;
    const int w       = tid >> 5;
    const int lane    = tid & 31;
    const int rowbase = blk * ROWS;

    unsigned int gen = 0;
    if (tid == 0) gen = *((volatile unsigned int*)&g_bar_gen);  // stable pre-barrier

    // ---- load this block's 16 rows of R into SMEM (once) ----
    {
        const float4* Rg4 = (const float4*)Rg + (size_t)rowbase * (MM / 4);
        float4* Rs4 = (float4*)Rs;
        #pragma unroll 4
        for (int k = tid; k < ROWS * MM / 4; k += NTHREADS) Rs4[k] = Rg4[k];
    }

    // ---- T (4x4) into registers ----
    float Tr[16];
    #pragma unroll
    for (int i = 0; i < 16; i++) Tr[i] = Tg[i];

    // ---- per-lane rho state: lane 0 -> row 2w, lane 1 -> row 2w+1 ----
    const int myrow = rowbase + 2 * w + lane;   // meaningful for lane < 2
    float r0 = 0.f, r1 = 0.f, r2 = 0.f, r3 = 0.f, kk = 0.f;
    if (lane < 2) {
        r0 = rho0[myrow * 4 + 0];
        r1 = rho0[myrow * 4 + 1];
        r2 = rho0[myrow * 4 + 2];
        r3 = rho0[myrow * 4 + 3];
        __stcg(&g_x[myrow], r0);                // initial x = rho0[:,0]
    }
    __syncthreads();                            // Rs ready for column sums

    // ---- deterministic ntot: per-block column partials (no float atomics) ----
    for (int c = tid; c < MM; c += NTHREADS) {
        float s = 0.f;
        #pragma unroll
        for (int r = 0; r < ROWS; r++) s += Rs[r * MM + c];
        __stcg(&g_part[blk * MM + c], s);
    }

    gridsync(gen);                              // partials + g_x visible

    // ntot for own 16 columns (== own row indices), fixed summation order
    if (tid < ROWS) {
        const int c = rowbase + tid;
        float s = 0.f;
        for (int bb = 0; bb < NBLK; bb++) s += __ldcg(&g_part[bb * MM + c]);
        ntot_s[tid] = s;
    }
    __syncthreads();
    if (lane < 2) kk = -BETA_F / ntot_s[2 * w + lane];

    const float4* Rw0 = (const float4*)(Rs + (2 * w) * MM);
    const float4* Rw1 = (const float4*)(Rs + (2 * w + 1) * MM);
    float4* xs4 = (float4*)xs;

    double dAcc = 0.0;

    for (int t = 0; t < NSTEPS; t++) {
        // ================= Phase A: frac = R @ x, p = 1 - exp(-beta*frac/ntot)
        {
            const float4* gx4 = (const float4*)g_x;
            #pragma unroll
            for (int k = tid; k < MM / 4; k += NTHREADS) xs4[k] = __ldcg(gx4 + k);
        }
        __syncthreads();

        float a0 = 0.f, a1 = 0.f;
        #pragma unroll
        for (int j = 0; j < 16; j++) {
            const int c = j * 32 + lane;
            const float4 xv = xs4[c];
            const float4 u = Rw0[c];
            const float4 v = Rw1[c];
            a0 += u.x * xv.x + u.y * xv.y + u.z * xv.z + u.w * xv.w;
            a1 += v.x * xv.x + v.y * xv.y + v.z * xv.z + v.w * xv.w;
        }
        #pragma unroll
        for (int o = 16; o; o >>= 1) {
            a0 += __shfl_xor_sync(0xffffffffu, a0, o);
            a1 += __shfl_xor_sync(0xffffffffu, a1, o);
        }
        if (lane < 2) {
            const float fr = (lane == 0) ? a0 : a1;
            __stcg(&g_p[myrow], 1.0f - expf(kk * fr));
        }
        gridsync(gen);

        // ================= Phase B: nw = R @ p, compartment update, traj out
        {
            const float4* gp4 = (const float4*)g_p;
            #pragma unroll
            for (int k = tid; k < MM / 4; k += NTHREADS) xs4[k] = __ldcg(gp4 + k);
        }
        __syncthreads();

        float b0 = 0.f, b1 = 0.f;
        #pragma unroll
        for (int j = 0; j < 16; j++) {
            const int c = j * 32 + lane;
            const float4 xv = xs4[c];
            const float4 u = Rw0[c];
            const float4 v = Rw1[c];
            b0 += u.x * xv.x + u.y * xv.y + u.z * xv.z + u.w * xv.w;
            b1 += v.x * xv.x + v.y * xv.y + v.z * xv.z + v.w * xv.w;
        }
        #pragma unroll
        for (int o = 16; o; o >>= 1) {
            b0 += __shfl_xor_sync(0xffffffffu, b0, o);
            b1 += __shfl_xor_sync(0xffffffffu, b1, o);
        }
        if (lane < 2) {
            const float acc = (lane == 0) ? b0 : b1;
            const float s   = r0 + r1 + r2 + r3;
            const float nw  = (1.0f - s) * acc;
            float n0 = r0 * Tr[0] + r1 * Tr[4] + r2 * Tr[8]  + r3 * Tr[12] + nw;
            float n1 = r0 * Tr[1] + r1 * Tr[5] + r2 * Tr[9]  + r3 * Tr[13];
            float n2 = r0 * Tr[2] + r1 * Tr[6] + r2 * Tr[10] + r3 * Tr[14];
            float n3 = r0 * Tr[3] + r1 * Tr[7] + r2 * Tr[11] + r3 * Tr[15];
            n0 = fminf(fmaxf(n0, 0.0f), 1e10f);
            n1 = fminf(fmaxf(n1, 0.0f), 1e10f);
            n2 = fminf(fmaxf(n2, 0.0f), 1e10f);
            n3 = fminf(fmaxf(n3, 0.0f), 1e10f);
            r0 = n0; r1 = n1; r2 = n2; r3 = n3;
            __stcg(&g_x[myrow], n0);                      // next step's x

            const float S = 1.0f - (n0 + n1 + n2 + n3);   // AddSusceptibleLayer
            float* o = out + ((size_t)t * MM + myrow) * (NC + 1);
            o[0] = S; o[1] = n0; o[2] = n1; o[3] = n2; o[4] = n3;
            dAcc += (double)(fabsf(S) + fabsf(n0) + fabsf(n1) + fabsf(n2) + fabsf(n3));
        }
        gridsync(gen);
    }

    // ---- agreement = mean(|traj|), fully deterministic reduction ----
    if (lane < 2) dsum[2 * w + lane] = dAcc;
    __syncthreads();
    if (tid == 0) {
        double s = 0.0;
        for (int i = 0; i < 16; i++) s += dsum[i];
        __stcg(&g_bsum[blk], s);
    }
    gridsync(gen);
    if (blk == 0 && tid == 0 && out_size > TRAJ_ELEMS) {
        double s = 0.0;
        for (int i = 0; i < NBLK; i++) s += __ldcg(&g_bsum[i]);
        out[TRAJ_ELEMS] = (float)(s / (double)TRAJ_ELEMS);
    }
}

extern "C" void kernel_launch(void* const* d_in, const int* in_sizes, int n_in,
                              void* d_out, int out_size)
{
    // Identify inputs by element count: R: 2048*2048, T: 4*4, rho0: 2048*4
    const float* R    = nullptr;
    const float* Tm   = nullptr;
    const float* rho0 = nullptr;
    for (int i = 0; i < n_in; i++) {
        if      (in_sizes[i] == MM * MM) R    = (const float*)d_in[i];
        else if (in_sizes[i] == NC * NC) Tm   = (const float*)d_in[i];
        else if (in_sizes[i] == MM * NC) rho0 = (const float*)d_in[i];
    }
    if (!R    && n_in > 0) R    = (const float*)d_in[0];
    if (!Tm   && n_in > 1) Tm   = (const float*)d_in[1];
    if (!rho0 && n_in > 2) rho0 = (const float*)d_in[2];

    cudaFuncSetAttribute(metasim_kernel,
                         cudaFuncAttributeMaxDynamicSharedMemorySize,
                         SMEM_BYTES);

    metasim_kernel<<<NBLK, NTHREADS, SMEM_BYTES>>>(R, Tm, rho0,
                                                   (float*)d_out, out_size);
}